// round 2
// baseline (speedup 1.0000x reference)
#include <cuda_runtime.h>
#include <cuda_bf16.h>
#include <cstdint>

#define NB 32
#define NC 384
#define NT 1024
#define MAXLEN 8192
#define COUT (NC + 2)
#define MAX_DUR 10000

// Scratch: per-position expansion map + per-batch totals.
// map element: .x = (tok << 1) | valid, .y = idx_in | (len << 16)
__device__ int2 g_map[NB * MAXLEN];
__device__ int  g_total[NB];
__device__ int  g_is64;

// ---------------------------------------------------------------------------
// Kernel 0: detect int64 vs int32 storage of `duration` (values are 0..7,
// so for int64 every odd 32-bit word of the first 1024 entries is zero).
// ---------------------------------------------------------------------------
__global__ void detect_kernel(const int* __restrict__ dur) {
    int odd_nonzero = 0;
    for (int i = threadIdx.x; i < 1024; i += 32) {
        if (dur[2 * i + 1] != 0) odd_nonzero = 1;
    }
    odd_nonzero = __any_sync(0xffffffffu, odd_nonzero);
    if (threadIdx.x == 0) g_is64 = odd_nonzero ? 0 : 1;
}

// ---------------------------------------------------------------------------
// Kernel 1: per-batch inclusive scan of clipped durations + scatter of the
// position->token expansion map. One block per batch, 1024 threads.
// ---------------------------------------------------------------------------
__global__ void scan_expand_kernel(const int* __restrict__ dur32) {
    const int b = blockIdx.x;
    const int t = threadIdx.x;
    const int lane = t & 31;
    const int warp = t >> 5;

    int d;
    if (g_is64) d = dur32[2 * (b * NT + t)];
    else        d = dur32[b * NT + t];
    if (d < 0) d = -d;
    if (d < 1) d = 1;
    if (d > MAX_DUR) d = MAX_DUR;

    int v = d;
    #pragma unroll
    for (int o = 1; o < 32; o <<= 1) {
        int n = __shfl_up_sync(0xffffffffu, v, o);
        if (lane >= o) v += n;
    }
    __shared__ int wsum[32];
    if (lane == 31) wsum[warp] = v;
    __syncthreads();
    if (warp == 0) {
        int w = wsum[lane];
        #pragma unroll
        for (int o = 1; o < 32; o <<= 1) {
            int n = __shfl_up_sync(0xffffffffu, w, o);
            if (lane >= o) w += n;
        }
        wsum[lane] = w;
    }
    __syncthreads();

    const int end_  = v + (warp > 0 ? wsum[warp - 1] : 0);
    const int start = end_ - d;

    __shared__ int s_total;
    if (t == NT - 1) {
        s_total = end_;
        g_total[b] = end_;
    }
    __syncthreads();
    const int total = s_total;

    int2* map = g_map + b * MAXLEN;

    for (int j = 0; j < d; j++) {
        const int pos = start + j;
        if (pos >= MAXLEN) break;
        map[pos] = make_int2((t << 1) | 1, j | (d << 16));
    }
    const int tstart = total < MAXLEN ? total : MAXLEN;
    for (int pos = tstart + t; pos < MAXLEN; pos += NT) {
        map[pos] = make_int2(0, 0);
    }
}

// ---------------------------------------------------------------------------
// Kernel 2: gather + write output, smem-staged.
// Block = 256 threads, 4 consecutive positions each (1024 positions/block).
// tok is monotone within the block -> contiguous token segment [tokmin,tokmax]
// staged into smem per channel with coalesced loads; reads via LDS; float4
// stores. Double buffer -> one __syncthreads per channel.
// Grid: (8 p-tiles, 32 batches, 4 channel chunks).
// ---------------------------------------------------------------------------
#define CCHUNK 97   // ceil(386/4)

__global__ void __launch_bounds__(256) gather_kernel(const float* __restrict__ x,
                                                     float* __restrict__ out) {
    __shared__ float buf[2][1024];
    __shared__ int s_min[8], s_max[8];

    const int b   = blockIdx.y;
    const int tid = threadIdx.x;
    const int p0  = (blockIdx.x * 256 + tid) * 4;

    const int4* mp = reinterpret_cast<const int4*>(g_map + b * MAXLEN + p0);
    const int4 m0 = mp[0];
    const int4 m1 = mp[1];

    const int v0 = m0.x & 1, v1 = m0.z & 1, v2 = m1.x & 1, v3 = m1.z & 1;
    const int tok0 = m0.x >> 1, tok1 = m0.z >> 1;
    const int tok2 = m1.x >> 1, tok3 = m1.z >> 1;
    const float f0 = v0 ? 1.f : 0.f;
    const float f1 = v1 ? 1.f : 0.f;
    const float f2 = v2 ? 1.f : 0.f;
    const float f3 = v3 ? 1.f : 0.f;

    // block-wide min/max over valid tokens (tok monotone -> contiguous range)
    int tmin = 0x7fffffff, tmax = -1;
    if (v0) { tmin = min(tmin, tok0); tmax = max(tmax, tok0); }
    if (v3) { tmin = min(tmin, tok3); tmax = max(tmax, tok3); }
    if (v1) { tmin = min(tmin, tok1); tmax = max(tmax, tok1); }
    if (v2) { tmin = min(tmin, tok2); tmax = max(tmax, tok2); }
    #pragma unroll
    for (int o = 16; o > 0; o >>= 1) {
        tmin = min(tmin, __shfl_xor_sync(0xffffffffu, tmin, o));
        tmax = max(tmax, __shfl_xor_sync(0xffffffffu, tmax, o));
    }
    if ((tid & 31) == 0) { s_min[tid >> 5] = tmin; s_max[tid >> 5] = tmax; }
    __syncthreads();
    tmin = s_min[0]; tmax = s_max[0];
    #pragma unroll
    for (int w = 1; w < 8; w++) { tmin = min(tmin, s_min[w]); tmax = max(tmax, s_max[w]); }

    const int nseg = tmax - tmin + 1;   // <= 1024; <= 0 if no valid position

    // per-thread smem indices (safe defaults when invalid)
    const int i0 = v0 ? (tok0 - tmin) : 0;
    const int i1 = v1 ? (tok1 - tmin) : 0;
    const int i2 = v2 ? (tok2 - tmin) : 0;
    const int i3 = v3 ? (tok3 - tmin) : 0;

    const float* xb = x + (size_t)b * NC * NT;
    float* ob = out + (size_t)b * COUT * MAXLEN + p0;

    const int cbeg = blockIdx.z * CCHUNK;
    const int cend = min(cbeg + CCHUNK, COUT);
    const int clim = min(cend, NC);

    if (nseg > 0) {
        int par = 0;
        for (int c = cbeg; c < clim; c++, par ^= 1) {
            const float* seg = xb + (size_t)c * NT + tmin;
            for (int i = tid; i < nseg; i += 256) buf[par][i] = seg[i];
            __syncthreads();
            float4 r;
            r.x = buf[par][i0] * f0;
            r.y = buf[par][i1] * f1;
            r.z = buf[par][i2] * f2;
            r.w = buf[par][i3] * f3;
            *reinterpret_cast<float4*>(ob + (size_t)c * MAXLEN) = r;
        }
    } else {
        const float4 z = make_float4(0.f, 0.f, 0.f, 0.f);
        for (int c = cbeg; c < clim; c++)
            *reinterpret_cast<float4*>(ob + (size_t)c * MAXLEN) = z;
    }

    if (NC >= cbeg && NC < cend) {
        float4 r;
        r.x = (float)(m0.y & 0xffff) * f0;
        r.y = (float)(m0.w & 0xffff) * f1;
        r.z = (float)(m1.y & 0xffff) * f2;
        r.w = (float)(m1.w & 0xffff) * f3;
        *reinterpret_cast<float4*>(ob + (size_t)NC * MAXLEN) = r;
    }
    if (NC + 1 >= cbeg && NC + 1 < cend) {
        float4 r;
        r.x = (float)((unsigned)m0.y >> 16) * f0;
        r.y = (float)((unsigned)m0.w >> 16) * f1;
        r.z = (float)((unsigned)m1.y >> 16) * f2;
        r.w = (float)((unsigned)m1.w >> 16) * f3;
        *reinterpret_cast<float4*>(ob + (size_t)(NC + 1) * MAXLEN) = r;
    }
}

// ---------------------------------------------------------------------------
// Kernel 3: mel_len output (cast to output dtype = float)
// ---------------------------------------------------------------------------
__global__ void mel_kernel(float* __restrict__ dst) {
    const int b = threadIdx.x;
    if (b < NB) dst[b] = (float)g_total[b];
}

extern "C" void kernel_launch(void* const* d_in, const int* in_sizes, int n_in,
                              void* d_out, int out_size) {
    const float* x   = (const float*)d_in[0];
    const int*   dur = (const int*)d_in[1];
    float*       out = (float*)d_out;

    detect_kernel<<<1, 32>>>(dur);
    scan_expand_kernel<<<NB, NT>>>(dur);
    gather_kernel<<<dim3(MAXLEN / (256 * 4), NB, 4), 256>>>(x, out);

    const long long main_elems = (long long)NB * COUT * MAXLEN;
    if ((long long)out_size >= main_elems + NB) {
        mel_kernel<<<1, 32>>>(out + main_elems);
    }
    (void)in_sizes; (void)n_in;
}

// round 3
// speedup vs baseline: 1.6527x; 1.6527x over previous
#include <cuda_runtime.h>
#include <cuda_bf16.h>
#include <cstdint>

#define NB 32
#define NC 384
#define NT 1024
#define MAXLEN 8192
#define COUT (NC + 2)
#define MAX_DUR 10000
#define MAIN_ELEMS ((long long)NB * COUT * MAXLEN)

// Scratch: per-position expansion map.
// map element: .x = (tok << 1) | valid, .y = idx_in | (len << 16)
__device__ int2 g_map[NB * MAXLEN];

// ---------------------------------------------------------------------------
// Kernel 1: fused per-batch detect(int64 vs int32) + inclusive scan of
// clipped durations + scatter of the position->token map + mel_len write.
// One block per batch, 1024 threads (one per token).
// ---------------------------------------------------------------------------
__global__ void scan_expand_kernel(const int* __restrict__ dur32,
                                   float* __restrict__ mel_dst) {
    const int b = blockIdx.x;
    const int t = threadIdx.x;
    const int lane = t & 31;
    const int warp = t >> 5;

    // dtype detect: inspect batch-0's first 1024 entries only (indices < 2048,
    // in-bounds for both layouts). If int64, every odd word is 0 (values 0..7).
    const int odd = dur32[2 * t + 1];
    const int is32 = __syncthreads_or(odd != 0);

    int d = is32 ? dur32[b * NT + t] : dur32[2 * (b * NT + t)];
    if (d < 0) d = -d;
    if (d < 1) d = 1;
    if (d > MAX_DUR) d = MAX_DUR;

    // block inclusive scan
    int v = d;
    #pragma unroll
    for (int o = 1; o < 32; o <<= 1) {
        int n = __shfl_up_sync(0xffffffffu, v, o);
        if (lane >= o) v += n;
    }
    __shared__ int wsum[32];
    if (lane == 31) wsum[warp] = v;
    __syncthreads();
    if (warp == 0) {
        int w = wsum[lane];
        #pragma unroll
        for (int o = 1; o < 32; o <<= 1) {
            int n = __shfl_up_sync(0xffffffffu, w, o);
            if (lane >= o) w += n;
        }
        wsum[lane] = w;
    }
    __syncthreads();

    const int end_  = v + (warp > 0 ? wsum[warp - 1] : 0);
    const int start = end_ - d;

    __shared__ int s_total;
    if (t == NT - 1) {
        s_total = end_;
        if (mel_dst) mel_dst[b] = (float)end_;
    }
    __syncthreads();
    const int total = s_total;

    int2* map = g_map + b * MAXLEN;

    // scatter: token t owns positions [start, end) — disjoint across threads
    for (int j = 0; j < d; j++) {
        const int pos = start + j;
        if (pos >= MAXLEN) break;
        map[pos] = make_int2((t << 1) | 1, j | (d << 16));
    }
    // tail: positions >= total are invalid
    const int tstart = total < MAXLEN ? total : MAXLEN;
    for (int pos = tstart + t; pos < MAXLEN; pos += NT) {
        map[pos] = make_int2(0, 0);
    }
}

// ---------------------------------------------------------------------------
// Kernel 2: gather + write output. Each thread owns 4 consecutive positions
// (float4 stores) and iterates a 96-channel chunk unrolled by 4, so 16
// independent gathered LDGs are in flight before the 4 stores (MLP ~16).
// Grid: (8 p-tiles, 32 batches, 4 channel chunks). z==3 also writes the two
// special rows (idx_in, length).
// ---------------------------------------------------------------------------
#define CCH 96

__global__ void __launch_bounds__(256) gather_kernel(const float* __restrict__ x,
                                                     float* __restrict__ out) {
    const int b   = blockIdx.y;
    const int tid = threadIdx.x;
    const int p0  = (blockIdx.x * 256 + tid) * 4;

    const int4* mp = reinterpret_cast<const int4*>(g_map + b * MAXLEN + p0);
    const int4 m0 = mp[0];
    const int4 m1 = mp[1];

    const int tok0 = m0.x >> 1, tok1 = m0.z >> 1;
    const int tok2 = m1.x >> 1, tok3 = m1.z >> 1;
    const float f0 = (m0.x & 1) ? 1.f : 0.f;
    const float f1 = (m0.z & 1) ? 1.f : 0.f;
    const float f2 = (m1.x & 1) ? 1.f : 0.f;
    const float f3 = (m1.w, m1.x & 1) ? 1.f : 0.f;   // see fix below
    // (re-derive f3 cleanly to avoid any comma-operator surprise)
    const float f3c = (m1.z & 1) ? 1.f : 0.f;

    const float* xb = x + (size_t)b * NC * NT;
    float* ob = out + (size_t)b * COUT * MAXLEN + p0;

    const int cbeg = blockIdx.z * CCH;

    #pragma unroll 1
    for (int c = cbeg; c < cbeg + CCH; c += 4) {
        const float* r0 = xb + (size_t)c * NT;
        const float* r1 = r0 + NT;
        const float* r2 = r1 + NT;
        const float* r3 = r2 + NT;

        // 16 independent loads
        const float a0 = r0[tok0], a1 = r0[tok1], a2 = r0[tok2], a3 = r0[tok3];
        const float b0 = r1[tok0], b1 = r1[tok1], b2 = r1[tok2], b3 = r1[tok3];
        const float c0 = r2[tok0], c1 = r2[tok1], c2 = r2[tok2], c3 = r2[tok3];
        const float d0 = r3[tok0], d1 = r3[tok1], d2 = r3[tok2], d3 = r3[tok3];

        float* o0 = ob + (size_t)c * MAXLEN;
        *reinterpret_cast<float4*>(o0) =
            make_float4(a0 * f0, a1 * f1, a2 * f2, a3 * f3c);
        *reinterpret_cast<float4*>(o0 + MAXLEN) =
            make_float4(b0 * f0, b1 * f1, b2 * f2, b3 * f3c);
        *reinterpret_cast<float4*>(o0 + 2 * MAXLEN) =
            make_float4(c0 * f0, c1 * f1, c2 * f2, c3 * f3c);
        *reinterpret_cast<float4*>(o0 + 3 * MAXLEN) =
            make_float4(d0 * f0, d1 * f1, d2 * f2, d3 * f3c);
    }

    if (blockIdx.z == 3) {
        // row NC: idx_in, row NC+1: length
        *reinterpret_cast<float4*>(ob + (size_t)NC * MAXLEN) =
            make_float4((float)(m0.y & 0xffff) * f0,
                        (float)(m0.w & 0xffff) * f1,
                        (float)(m1.y & 0xffff) * f2,
                        (float)(m1.w & 0xffff) * f3c);
        *reinterpret_cast<float4*>(ob + (size_t)(NC + 1) * MAXLEN) =
            make_float4((float)((unsigned)m0.y >> 16) * f0,
                        (float)((unsigned)m0.w >> 16) * f1,
                        (float)((unsigned)m1.y >> 16) * f2,
                        (float)((unsigned)m1.w >> 16) * f3c);
    }
    (void)f3;
}

extern "C" void kernel_launch(void* const* d_in, const int* in_sizes, int n_in,
                              void* d_out, int out_size) {
    const float* x   = (const float*)d_in[0];
    const int*   dur = (const int*)d_in[1];
    float*       out = (float*)d_out;

    float* mel = ((long long)out_size >= MAIN_ELEMS + NB) ? (out + MAIN_ELEMS)
                                                          : nullptr;

    scan_expand_kernel<<<NB, NT>>>(dur, mel);
    gather_kernel<<<dim3(MAXLEN / (256 * 4), NB, 4), 256>>>(x, out);

    (void)in_sizes; (void)n_in;
}

// round 4
// speedup vs baseline: 1.8827x; 1.1391x over previous
#include <cuda_runtime.h>
#include <cuda_bf16.h>
#include <cstdint>

#define NB 32
#define NC 384
#define NT 1024
#define MAXLEN 8192
#define COUT (NC + 2)
#define MAX_DUR 10000
#define MAIN_ELEMS ((long long)NB * COUT * MAXLEN)

// Scratch: per-position expansion map.
// map element: .x = (tok << 1) | valid, .y = idx_in | (len << 16)
__device__ int2 g_map[NB * MAXLEN];

// ---------------------------------------------------------------------------
// Kernel 1: fused detect(int64 vs int32) + per-batch inclusive scan of
// clipped durations + scatter of position->token map + mel_len write.
// One block per batch, 1024 threads (one per token).
// ---------------------------------------------------------------------------
__global__ void scan_expand_kernel(const int* __restrict__ dur32,
                                   float* __restrict__ mel_dst) {
    const int b = blockIdx.x;
    const int t = threadIdx.x;
    const int lane = t & 31;
    const int warp = t >> 5;

    // dtype detect on batch-0's first 1024 entries (in-bounds either way).
    // Values are 0..7, so int64 => every odd 32-bit word is zero.
    const int odd = dur32[2 * t + 1];
    const int is32 = __syncthreads_or(odd != 0);

    int d = is32 ? dur32[b * NT + t] : dur32[2 * (b * NT + t)];
    if (d < 0) d = -d;
    if (d < 1) d = 1;
    if (d > MAX_DUR) d = MAX_DUR;

    // block inclusive scan
    int v = d;
    #pragma unroll
    for (int o = 1; o < 32; o <<= 1) {
        int n = __shfl_up_sync(0xffffffffu, v, o);
        if (lane >= o) v += n;
    }
    __shared__ int wsum[32];
    if (lane == 31) wsum[warp] = v;
    __syncthreads();
    if (warp == 0) {
        int w = wsum[lane];
        #pragma unroll
        for (int o = 1; o < 32; o <<= 1) {
            int n = __shfl_up_sync(0xffffffffu, w, o);
            if (lane >= o) w += n;
        }
        wsum[lane] = w;
    }
    __syncthreads();

    const int end_  = v + (warp > 0 ? wsum[warp - 1] : 0);
    const int start = end_ - d;

    __shared__ int s_total;
    if (t == NT - 1) {
        s_total = end_;
        if (mel_dst) mel_dst[b] = (float)end_;
    }
    __syncthreads();
    const int total = s_total;

    int2* map = g_map + b * MAXLEN;

    for (int j = 0; j < d; j++) {
        const int pos = start + j;
        if (pos >= MAXLEN) break;
        map[pos] = make_int2((t << 1) | 1, j | (d << 16));
    }
    const int tstart = total < MAXLEN ? total : MAXLEN;
    for (int pos = tstart + t; pos < MAXLEN; pos += NT) {
        map[pos] = make_int2(0, 0);
    }
}

// ---------------------------------------------------------------------------
// Kernel 2: gather + write. Thread owns 4 consecutive positions (float4
// streaming stores, __stcs so the write-once output doesn't evict x from L2).
// Channel chunk = 32 per block, unrolled x4 => 16 independent LDGs in flight
// before the 4 stores of each group. Grid (8 p-tiles, 32 batches, 12 chunks)
// = 3072 blocks for good wave balance. z==11 also writes the 2 special rows.
// ---------------------------------------------------------------------------
#define CCH 32

__global__ void __launch_bounds__(256) gather_kernel(const float* __restrict__ x,
                                                     float* __restrict__ out) {
    const int b   = blockIdx.y;
    const int tid = threadIdx.x;
    const int p0  = (blockIdx.x * 256 + tid) * 4;

    const int4* mp = reinterpret_cast<const int4*>(g_map + b * MAXLEN + p0);
    const int4 m0 = mp[0];
    const int4 m1 = mp[1];

    const int tok0 = m0.x >> 1, tok1 = m0.z >> 1;
    const int tok2 = m1.x >> 1, tok3 = m1.z >> 1;
    const float f0 = (m0.x & 1) ? 1.f : 0.f;
    const float f1 = (m0.z & 1) ? 1.f : 0.f;
    const float f2 = (m1.x & 1) ? 1.f : 0.f;
    const float f3 = (m1.z & 1) ? 1.f : 0.f;

    const float* xb = x + (size_t)b * NC * NT;
    float* ob = out + (size_t)b * COUT * MAXLEN + p0;

    const int cbeg = blockIdx.z * CCH;

    #pragma unroll 1
    for (int c = cbeg; c < cbeg + CCH; c += 4) {
        const float* r0 = xb + (size_t)c * NT;
        const float* r1 = r0 + NT;
        const float* r2 = r1 + NT;
        const float* r3 = r2 + NT;

        const float a0 = r0[tok0], a1 = r0[tok1], a2 = r0[tok2], a3 = r0[tok3];
        const float b0 = r1[tok0], b1 = r1[tok1], b2 = r1[tok2], b3 = r1[tok3];
        const float c0 = r2[tok0], c1 = r2[tok1], c2 = r2[tok2], c3 = r2[tok3];
        const float d0 = r3[tok0], d1 = r3[tok1], d2 = r3[tok2], d3 = r3[tok3];

        float* o0 = ob + (size_t)c * MAXLEN;
        __stcs(reinterpret_cast<float4*>(o0),
               make_float4(a0 * f0, a1 * f1, a2 * f2, a3 * f3));
        __stcs(reinterpret_cast<float4*>(o0 + MAXLEN),
               make_float4(b0 * f0, b1 * f1, b2 * f2, b3 * f3));
        __stcs(reinterpret_cast<float4*>(o0 + 2 * MAXLEN),
               make_float4(c0 * f0, c1 * f1, c2 * f2, c3 * f3));
        __stcs(reinterpret_cast<float4*>(o0 + 3 * MAXLEN),
               make_float4(d0 * f0, d1 * f1, d2 * f2, d3 * f3));
    }

    if (blockIdx.z == 11) {
        __stcs(reinterpret_cast<float4*>(ob + (size_t)NC * MAXLEN),
               make_float4((float)(m0.y & 0xffff) * f0,
                           (float)(m0.w & 0xffff) * f1,
                           (float)(m1.y & 0xffff) * f2,
                           (float)(m1.w & 0xffff) * f3));
        __stcs(reinterpret_cast<float4*>(ob + (size_t)(NC + 1) * MAXLEN),
               make_float4((float)((unsigned)m0.y >> 16) * f0,
                           (float)((unsigned)m0.w >> 16) * f1,
                           (float)((unsigned)m1.y >> 16) * f2,
                           (float)((unsigned)m1.w >> 16) * f3));
    }
}

extern "C" void kernel_launch(void* const* d_in, const int* in_sizes, int n_in,
                              void* d_out, int out_size) {
    const float* x   = (const float*)d_in[0];
    const int*   dur = (const int*)d_in[1];
    float*       out = (float*)d_out;

    float* mel = ((long long)out_size >= MAIN_ELEMS + NB) ? (out + MAIN_ELEMS)
                                                          : nullptr;

    scan_expand_kernel<<<NB, NT>>>(dur, mel);
    gather_kernel<<<dim3(MAXLEN / (256 * 4), NB, 12), 256>>>(x, out);

    (void)in_sizes; (void)n_in;
}

// round 5
// speedup vs baseline: 1.9790x; 1.0512x over previous
#include <cuda_runtime.h>
#include <cuda_bf16.h>
#include <cstdint>

#define NB 32
#define NC 384
#define NT 1024
#define MAXLEN 8192
#define COUT (NC + 2)
#define MAX_DUR 10000
#define MAIN_ELEMS ((long long)NB * COUT * MAXLEN)
#define CCH 32   // channels per block

// ---------------------------------------------------------------------------
// Single fused kernel.
// Grid: (8 p-tiles, 32 batches, 12 channel chunks) = 3072 blocks, 256 threads.
// Each block: detect dtype -> load+clip its batch's 1024 durations ->
// block scan into smem ends[] -> per-thread token lookup for its 4 positions
// -> gather 32 channels, MLP-16 inner loop, float4 streaming stores.
// z==11 blocks also write the idx_in / length rows; (x==0,z==0) writes mel_len.
// ---------------------------------------------------------------------------
__global__ void __launch_bounds__(256) lr_kernel(const float* __restrict__ x,
                                                 const int* __restrict__ dur32,
                                                 float* __restrict__ out,
                                                 float* __restrict__ mel_dst) {
    __shared__ int sEnds[NT];
    __shared__ int wsum[8];

    const int b    = blockIdx.y;
    const int tid  = threadIdx.x;
    const int lane = tid & 31;
    const int warp = tid >> 5;
    const int t4   = tid * 4;            // this thread's 4 token slots

    // ---- dtype detect (batch 0, words 8*tid .. 8*tid+7; in-bounds either way)
    const int4* dw = reinterpret_cast<const int4*>(dur32);
    const int4 v0 = dw[2 * tid];
    const int4 v1 = dw[2 * tid + 1];
    const int odd = v0.y | v0.w | v1.y | v1.w;
    const int is32 = __syncthreads_or(odd != 0);

    // ---- load this batch's 4 durations
    int d0, d1, d2, d3;
    if (is32) {
        const int4 dv = reinterpret_cast<const int4*>(dur32 + b * NT)[tid];
        d0 = dv.x; d1 = dv.y; d2 = dv.z; d3 = dv.w;
    } else if (b == 0) {
        d0 = v0.x; d1 = v0.z; d2 = v1.x; d3 = v1.z;
    } else {
        const int4* p = reinterpret_cast<const int4*>(dur32) + 2 * (b * 512 + tid);
        const int4 a = p[0], c = p[1];
        d0 = a.x; d1 = a.z; d2 = c.x; d3 = c.z;
    }
    #define CLIP(v) { if (v < 0) v = -v; if (v < 1) v = 1; if (v > MAX_DUR) v = MAX_DUR; }
    CLIP(d0) CLIP(d1) CLIP(d2) CLIP(d3)
    #undef CLIP

    // ---- block scan of per-thread sums
    const int s4 = d0 + d1 + d2 + d3;
    int v = s4;
    #pragma unroll
    for (int o = 1; o < 32; o <<= 1) {
        int n = __shfl_up_sync(0xffffffffu, v, o);
        if (lane >= o) v += n;
    }
    if (lane == 31) wsum[warp] = v;
    __syncthreads();
    if (warp == 0 && lane < 8) {
        int w = wsum[lane];
        #pragma unroll
        for (int o = 1; o < 8; o <<= 1) {
            int n = __shfl_up_sync(0xffu, w, o);
            if (lane >= o) w += n;
        }
        wsum[lane] = w;
    }
    __syncthreads();

    int base = v - s4 + (warp > 0 ? wsum[warp - 1] : 0);  // exclusive prefix
    const int e0 = base + d0;
    const int e1 = e0 + d1;
    const int e2 = e1 + d2;
    const int e3 = e2 + d3;
    sEnds[t4]     = e0;
    sEnds[t4 + 1] = e1;
    sEnds[t4 + 2] = e2;
    sEnds[t4 + 3] = e3;
    __syncthreads();

    const int total = sEnds[NT - 1];
    if (mel_dst && blockIdx.x == 0 && blockIdx.z == 0 && tid == 0)
        mel_dst[b] = (float)total;

    // ---- token lookup for this thread's 4 output positions
    const int p0 = (blockIdx.x * 256 + tid) * 4;

    // tok = #{ends <= p}  (searchsorted right), branchless binary search
    int tok0 = 0;
    #pragma unroll
    for (int s = 512; s > 0; s >>= 1) {
        const int cand = tok0 + s;
        if (cand <= NT && sEnds[cand - 1] <= p0) tok0 = cand;
    }
    int tok1 = tok0; if (tok1 < NT && sEnds[tok1] <= p0 + 1) tok1++;
    int tok2 = tok1; if (tok2 < NT && sEnds[tok2] <= p0 + 2) tok2++;
    int tok3 = tok2; if (tok3 < NT && sEnds[tok3] <= p0 + 3) tok3++;

    const float f0 = (p0     < total) ? 1.f : 0.f;
    const float f1 = (p0 + 1 < total) ? 1.f : 0.f;
    const float f2 = (p0 + 2 < total) ? 1.f : 0.f;
    const float f3 = (p0 + 3 < total) ? 1.f : 0.f;

    if (tok0 > NT - 1) tok0 = NT - 1;
    if (tok1 > NT - 1) tok1 = NT - 1;
    if (tok2 > NT - 1) tok2 = NT - 1;
    if (tok3 > NT - 1) tok3 = NT - 1;

    const float* xb = x + (size_t)b * NC * NT;
    float* ob = out + (size_t)b * COUT * MAXLEN + p0;

    const int cbeg = blockIdx.z * CCH;

    #pragma unroll 1
    for (int c = cbeg; c < cbeg + CCH; c += 4) {
        const float* r0 = xb + (size_t)c * NT;
        const float* r1 = r0 + NT;
        const float* r2 = r1 + NT;
        const float* r3 = r2 + NT;

        const float a0 = r0[tok0], a1 = r0[tok1], a2 = r0[tok2], a3 = r0[tok3];
        const float b0 = r1[tok0], b1 = r1[tok1], b2 = r1[tok2], b3 = r1[tok3];
        const float c0 = r2[tok0], c1 = r2[tok1], c2 = r2[tok2], c3 = r2[tok3];
        const float e0_ = r3[tok0], e1_ = r3[tok1], e2_ = r3[tok2], e3_ = r3[tok3];

        float* o0 = ob + (size_t)c * MAXLEN;
        __stcs(reinterpret_cast<float4*>(o0),
               make_float4(a0 * f0, a1 * f1, a2 * f2, a3 * f3));
        __stcs(reinterpret_cast<float4*>(o0 + MAXLEN),
               make_float4(b0 * f0, b1 * f1, b2 * f2, b3 * f3));
        __stcs(reinterpret_cast<float4*>(o0 + 2 * MAXLEN),
               make_float4(c0 * f0, c1 * f1, c2 * f2, c3 * f3));
        __stcs(reinterpret_cast<float4*>(o0 + 3 * MAXLEN),
               make_float4(e0_ * f0, e1_ * f1, e2_ * f2, e3_ * f3));
    }

    if (blockIdx.z == 11) {
        // lengths and starts from smem ends
        const int l0 = sEnds[tok0] - (tok0 ? sEnds[tok0 - 1] : 0);
        const int l1 = sEnds[tok1] - (tok1 ? sEnds[tok1 - 1] : 0);
        const int l2 = sEnds[tok2] - (tok2 ? sEnds[tok2 - 1] : 0);
        const int l3 = sEnds[tok3] - (tok3 ? sEnds[tok3 - 1] : 0);
        const int i0 = p0     - (sEnds[tok0] - l0);
        const int i1 = p0 + 1 - (sEnds[tok1] - l1);
        const int i2 = p0 + 2 - (sEnds[tok2] - l2);
        const int i3 = p0 + 3 - (sEnds[tok3] - l3);

        __stcs(reinterpret_cast<float4*>(ob + (size_t)NC * MAXLEN),
               make_float4((float)i0 * f0, (float)i1 * f1,
                           (float)i2 * f2, (float)i3 * f3));
        __stcs(reinterpret_cast<float4*>(ob + (size_t)(NC + 1) * MAXLEN),
               make_float4((float)l0 * f0, (float)l1 * f1,
                           (float)l2 * f2, (float)l3 * f3));
    }
}

extern "C" void kernel_launch(void* const* d_in, const int* in_sizes, int n_in,
                              void* d_out, int out_size) {
    const float* x   = (const float*)d_in[0];
    const int*   dur = (const int*)d_in[1];
    float*       out = (float*)d_out;

    float* mel = ((long long)out_size >= MAIN_ELEMS + NB) ? (out + MAIN_ELEMS)
                                                          : nullptr;

    lr_kernel<<<dim3(MAXLEN / (256 * 4), NB, 12), 256>>>(x, dur, out, mel);

    (void)in_sizes; (void)n_in;
}